// round 13
// baseline (speedup 1.0000x reference)
#include <cuda_runtime.h>
#include <cuda_fp16.h>

// Causal SDPA, B=4 H=16 S=2048 D=64, fp32.
// R11 (re-bench; prior submission hit GPU-broker timeout): 512-thread CTA,
// 16 warps = 2x occupancy (4 warps/SMSP). Warp (wm,wn): wm = 16-row Q block,
// wn = KV n-half. QK m16n32k64/warp (acc halved), per-warp partial-O PV
// m16d64k32, cross-warp row stats + O-sum via smem. Q in permuted smem (no
// 32-reg qf), double-buffered K/V, 2 barriers/tile. tf32 QK + fp16 PV
// mma.sync, log2-domain softmax, poly exp2 on fma pipe.

namespace {

constexpr int Sc = 2048;
constexpr int Dc = 64;
constexpr int BM = 128;
constexpr int BN = 64;
constexpr int NT = 512;
constexpr int QROW = 80;  // permuted row strides (u32 words)
constexpr int KROW = 80;
constexpr int VROW = 48;

// smem layout (u32 words)
constexpr int QP_OFF = 0;                       // 128*80 = 10240
constexpr int KP_OFF = QP_OFF + 128 * QROW;     // 2 bufs * 64*80 = 10240
constexpr int VP_OFF = KP_OFF + 2 * 64 * KROW;  // 2 bufs * 64*48 = 6144
constexpr int RM_OFF = VP_OFF + 2 * 64 * VROW;  // 256
constexpr int RS_OFF = RM_OFF + 256;            // 256
constexpr int SMEM_WORDS = RS_OFF + 256;        // 27136 words = 108544 B

#define QSCALE 0.180336880111120430f  // (1/sqrt(64)) * log2(e)
#define MAGICF 12582912.0f            // 1.5 * 2^23
#define EC1 0.6931471805599453f
#define EC2 0.2402265069591007f
#define EC3 0.0555041086648216f
#define EC4 0.0096181291076285f

typedef unsigned long long u64;
typedef unsigned int u32;

__device__ __forceinline__ u64 pack2(float lo, float hi) {
  u64 r;
  asm("mov.b64 %0, {%1, %2};" : "=l"(r) : "f"(lo), "f"(hi));
  return r;
}
__device__ __forceinline__ void unpack2(u64 v, float& lo, float& hi) {
  asm("mov.b64 {%0, %1}, %2;" : "=f"(lo), "=f"(hi) : "l"(v));
}
__device__ __forceinline__ u64 fma2o(u64 a, u64 b, u64 c) {
  u64 d;
  asm("fma.rn.f32x2 %0, %1, %2, %3;" : "=l"(d) : "l"(a), "l"(b), "l"(c));
  return d;
}
__device__ __forceinline__ u64 add2(u64 a, u64 b) {
  u64 d;
  asm("add.rn.f32x2 %0, %1, %2;" : "=l"(d) : "l"(a), "l"(b));
  return d;
}

__device__ __forceinline__ float exp2s(float d) {
  d = fmaxf(d, -80.0f);
  float t = d + MAGICF;
  float nf = t - MAGICF;
  float f = d - nf;
  float p = EC3 + f * EC4;
  p = EC2 + f * p;
  p = EC1 + f * p;
  p = 1.0f + f * p;
  return __int_as_float(__float_as_int(p) + (__float_as_int(t) << 23));
}

__device__ __forceinline__ void exp2p2(float d0, float d1, float& e0, float& e1) {
  u64 d2 = pack2(d0, d1);
  u64 t2 = add2(d2, pack2(MAGICF, MAGICF));
  u64 n2 = add2(t2, pack2(-MAGICF, -MAGICF));
  u64 f2 = fma2o(n2, pack2(-1.0f, -1.0f), d2);
  u64 p2 = fma2o(f2, pack2(EC4, EC4), pack2(EC3, EC3));
  p2 = fma2o(f2, p2, pack2(EC2, EC2));
  p2 = fma2o(f2, p2, pack2(EC1, EC1));
  p2 = fma2o(f2, p2, pack2(1.0f, 1.0f));
  float tf0, tf1, pf0, pf1;
  unpack2(t2, tf0, tf1);
  unpack2(p2, pf0, pf1);
  e0 = __int_as_float(__float_as_int(pf0) + (__float_as_int(tf0) << 23));
  e1 = __int_as_float(__float_as_int(pf1) + (__float_as_int(tf1) << 23));
}

__device__ __forceinline__ u32 cvt_tf32(float x) {
  u32 r;
  asm("cvt.rna.tf32.f32 %0, %1;" : "=r"(r) : "f"(x));
  return r;
}
__device__ __forceinline__ u32 h2pack(float lo, float hi) {
  __half2 h = __floats2half2_rn(lo, hi);
  return *reinterpret_cast<u32*>(&h);
}

__device__ __forceinline__ void mma_tf32(float& c0, float& c1, float& c2, float& c3,
                                         u32 a0, u32 a1, u32 a2, u32 a3,
                                         u32 b0, u32 b1) {
  asm("mma.sync.aligned.m16n8k8.row.col.f32.tf32.tf32.f32 "
      "{%0,%1,%2,%3}, {%4,%5,%6,%7}, {%8,%9}, {%0,%1,%2,%3};"
      : "+f"(c0), "+f"(c1), "+f"(c2), "+f"(c3)
      : "r"(a0), "r"(a1), "r"(a2), "r"(a3), "r"(b0), "r"(b1));
}
__device__ __forceinline__ void mma_f16(float& c0, float& c1, float& c2, float& c3,
                                        u32 a0, u32 a1, u32 a2, u32 a3,
                                        u32 b0, u32 b1) {
  asm("mma.sync.aligned.m16n8k16.row.col.f32.f16.f16.f32 "
      "{%0,%1,%2,%3}, {%4,%5,%6,%7}, {%8,%9}, {%0,%1,%2,%3};"
      : "+f"(c0), "+f"(c1), "+f"(c2), "+f"(c3)
      : "r"(a0), "r"(a1), "r"(a2), "r"(a3), "r"(b0), "r"(b1));
}

__global__ __launch_bounds__(NT, 1) void fa_fwd(
    const float* __restrict__ Qg, const float* __restrict__ Kg,
    const float* __restrict__ Vg, float* __restrict__ Og) {
  extern __shared__ __align__(16) u32 sm[];
  u32* Qp = sm + QP_OFF;
  float* redM = (float*)(sm + RM_OFF);
  float* redS = (float*)(sm + RS_OFF);

  const int tid = threadIdx.x;
  const int w = tid >> 5;
  const int lane = tid & 31;
  const int wm = w & 7;      // 16-row block
  const int wn = w >> 3;     // KV n-half (0/1)
  const int g = lane >> 2;
  const int tq = lane & 3;
  const int qt = 15 - (int)blockIdx.x;  // long CTAs first
  const int q0 = qt * BM;
  const size_t bh = blockIdx.y;
  const float* Qb = Qg + (bh * Sc + q0) * (size_t)Dc;
  const float* Kb = Kg + bh * (size_t)(Sc * Dc);
  const float* Vb = Vg + bh * (size_t)(Sc * Dc);
  const int ntiles = 2 * qt + 2;

  // ---- stage Q once: permuted (class = c%4 at stride 20), prescaled ----
  {
    int r = tid >> 2, b = tid & 3;  // row, 16-col block
    const float* qrow = Qb + (size_t)r * Dc + 16 * b;
    u32* dst = Qp + QROW * r;
#pragma unroll
    for (int e4 = 0; e4 < 4; ++e4) {
      float4 v = *(const float4*)(qrow + 4 * e4);
      int pos = 4 * b + e4;  // c/4 for c = 16b+4e4 (+u in class u)
      dst[pos] = cvt_tf32(v.x * QSCALE);
      dst[20 + pos] = cvt_tf32(v.y * QSCALE);
      dst[40 + pos] = cvt_tf32(v.z * QSCALE);
      dst[60 + pos] = cvt_tf32(v.w * QSCALE);
    }
  }

  // K/V staging maps (split across 512 threads; 8 elems each)
  const int kr = tid >> 3, kb = tid & 7;             // K: row kr, cols 8kb..8kb+7
  const int vn = (tid & 31) << 1;                    // V: rows vn, vn+1
  const int vd = (tid >> 5) << 2;                    // V: cols vd..vd+3

  // ---- stage tile 0 into buffer 0 ----
  float4 ka, ka2, va, va2;
  ka = *(const float4*)(Kb + (size_t)kr * Dc + 8 * kb);
  ka2 = *(const float4*)(Kb + (size_t)kr * Dc + 8 * kb + 4);
  va = *(const float4*)(Vb + (size_t)vn * Dc + vd);
  va2 = *(const float4*)(Vb + (size_t)(vn + 1) * Dc + vd);
  {
    u32* kd = sm + KP_OFF + KROW * kr + 2 * kb;
    kd[0] = cvt_tf32(ka.x); kd[20] = cvt_tf32(ka.y);
    kd[40] = cvt_tf32(ka.z); kd[60] = cvt_tf32(ka.w);
    kd[1] = cvt_tf32(ka2.x); kd[21] = cvt_tf32(ka2.y);
    kd[41] = cvt_tf32(ka2.z); kd[61] = cvt_tf32(ka2.w);
    int i = vn >> 1;
#pragma unroll
    for (int j = 0; j < 4; ++j) {
      int r = vd + j;
      sm[VP_OFF + VROW * r + 12 * ((i & 3) ^ (r & 3)) + (i >> 2)] =
          h2pack((&va.x)[j], (&va2.x)[j]);
    }
  }
  __syncthreads();

  const int r0 = q0 + 16 * wm + g;  // this thread's rows: r0, r0+8
  const u32* qbA = Qp + QROW * (16 * wm + g) + 20 * tq;
  const u32* qbB = qbA + QROW * 8;

  float O[8][4];
#pragma unroll
  for (int dt = 0; dt < 8; ++dt)
#pragma unroll
    for (int c = 0; c < 4; ++c) O[dt][c] = 0.f;
  float m0 = -1e30f, m1 = -1e30f, l0 = 0.f, l1 = 0.f;

  for (int t = 0; t < ntiles; ++t) {
    const int buf = t & 1;
    const int n0 = t * BN;

    // prefetch gmem for tile t+1 (stored between bar_A and bar_B)
    const bool havenext = (t + 1 < ntiles);
    if (havenext) {
      const int nn = (t + 1) * BN;
      ka = *(const float4*)(Kb + (size_t)(nn + kr) * Dc + 8 * kb);
      ka2 = *(const float4*)(Kb + (size_t)(nn + kr) * Dc + 8 * kb + 4);
      va = *(const float4*)(Vb + (size_t)(nn + vn) * Dc + vd);
      va2 = *(const float4*)(Vb + (size_t)(nn + vn + 1) * Dc + vd);
    }

    // ---- QK: m16 x n32 (this warp's half) x k64 ----
    float acc[4][4];
#pragma unroll
    for (int j = 0; j < 4; ++j)
#pragma unroll
      for (int c = 0; c < 4; ++c) acc[j][c] = 0.f;

    const u32* kbase = sm + KP_OFF + buf * (64 * KROW) +
                       KROW * (8 * 4 * wn + g) + 20 * tq;
#pragma unroll
    for (int mch = 0; mch < 4; ++mch) {
      uint4 qa = *reinterpret_cast<const uint4*>(qbA + 4 * mch);
      uint4 qb = *reinterpret_cast<const uint4*>(qbB + 4 * mch);
#pragma unroll
      for (int j = 0; j < 4; ++j) {
        uint4 kk = *reinterpret_cast<const uint4*>(kbase + KROW * 8 * j + 4 * mch);
        mma_tf32(acc[j][0], acc[j][1], acc[j][2], acc[j][3],
                 qa.x, qb.x, qa.y, qb.y, kk.x, kk.y);
        mma_tf32(acc[j][0], acc[j][1], acc[j][2], acc[j][3],
                 qa.z, qb.z, qa.w, qb.w, kk.z, kk.w);
      }
    }

    // ---- mask + partial row max over this warp's n-half ----
    if (t >= 2 * qt) {  // diagonal tiles
#pragma unroll
      for (int j = 0; j < 4; ++j) {
        int col = n0 + 8 * (4 * wn + j) + 2 * tq;
        if (col > r0) acc[j][0] = -1e30f;
        if (col + 1 > r0) acc[j][1] = -1e30f;
        if (col > r0 + 8) acc[j][2] = -1e30f;
        if (col + 1 > r0 + 8) acc[j][3] = -1e30f;
      }
    }
    float mt0 = fmaxf(acc[0][0], acc[0][1]), mt1 = fmaxf(acc[0][2], acc[0][3]);
#pragma unroll
    for (int j = 1; j < 4; ++j) {
      mt0 = fmaxf(mt0, fmaxf(acc[j][0], acc[j][1]));
      mt1 = fmaxf(mt1, fmaxf(acc[j][2], acc[j][3]));
    }
    mt0 = fmaxf(mt0, __shfl_xor_sync(0xffffffffu, mt0, 1));
    mt0 = fmaxf(mt0, __shfl_xor_sync(0xffffffffu, mt0, 2));
    mt1 = fmaxf(mt1, __shfl_xor_sync(0xffffffffu, mt1, 1));
    mt1 = fmaxf(mt1, __shfl_xor_sync(0xffffffffu, mt1, 2));
    if (tq == 0) {
      redM[wn * 128 + wm * 16 + g] = mt0;
      redM[wn * 128 + wm * 16 + 8 + g] = mt1;
    }
    __syncthreads();  // bar_A

    // ---- combine max, exp2, partial sums; stage t+1 into alt buffer ----
    mt0 = fmaxf(mt0, redM[(wn ^ 1) * 128 + wm * 16 + g]);
    mt1 = fmaxf(mt1, redM[(wn ^ 1) * 128 + wm * 16 + 8 + g]);
    const float mn0 = fmaxf(m0, mt0), mn1 = fmaxf(m1, mt1);
    const float al0 = exp2s(m0 - mn0), al1 = exp2s(m1 - mn1);
    m0 = mn0;
    m1 = mn1;

    float rs0 = 0.f, rs1 = 0.f;
    u32 h2lo[4], h2hi[4];
#pragma unroll
    for (int j = 0; j < 4; ++j) {
      float e0, e1, e2, e3;
      exp2p2(fmaxf(acc[j][0] - mn0, -80.f), fmaxf(acc[j][1] - mn0, -80.f), e0, e1);
      exp2p2(fmaxf(acc[j][2] - mn1, -80.f), fmaxf(acc[j][3] - mn1, -80.f), e2, e3);
      rs0 += e0 + e1;
      rs1 += e2 + e3;
      h2lo[j] = h2pack(e0, e1);
      h2hi[j] = h2pack(e2, e3);
    }
    rs0 += __shfl_xor_sync(0xffffffffu, rs0, 1);
    rs0 += __shfl_xor_sync(0xffffffffu, rs0, 2);
    rs1 += __shfl_xor_sync(0xffffffffu, rs1, 1);
    rs1 += __shfl_xor_sync(0xffffffffu, rs1, 2);
    if (tq == 0) {
      redS[wn * 128 + wm * 16 + g] = rs0;
      redS[wn * 128 + wm * 16 + 8 + g] = rs1;
    }

    if (havenext) {
      u32* kd = sm + KP_OFF + (buf ^ 1) * (64 * KROW) + KROW * kr + 2 * kb;
      kd[0] = cvt_tf32(ka.x); kd[20] = cvt_tf32(ka.y);
      kd[40] = cvt_tf32(ka.z); kd[60] = cvt_tf32(ka.w);
      kd[1] = cvt_tf32(ka2.x); kd[21] = cvt_tf32(ka2.y);
      kd[41] = cvt_tf32(ka2.z); kd[61] = cvt_tf32(ka2.w);
      int i = vn >> 1;
      u32* vdst = sm + VP_OFF + (buf ^ 1) * (64 * VROW);
#pragma unroll
      for (int j = 0; j < 4; ++j) {
        int r = vd + j;
        vdst[VROW * r + 12 * ((i & 3) ^ (r & 3)) + (i >> 2)] =
            h2pack((&va.x)[j], (&va2.x)[j]);
      }
    }
    __syncthreads();  // bar_B (redS ready AND t+1 buffers ready)

    rs0 += redS[(wn ^ 1) * 128 + wm * 16 + g];
    rs1 += redS[(wn ^ 1) * 128 + wm * 16 + 8 + g];
    l0 = l0 * al0 + rs0;
    l1 = l1 * al1 + rs1;
#pragma unroll
    for (int dt = 0; dt < 8; ++dt) {
      O[dt][0] *= al0;
      O[dt][1] *= al0;
      O[dt][2] *= al1;
      O[dt][3] *= al1;
    }

    // ---- PV: m16 x d64 x k32 (this warp's n-half), partial O ----
    const u32* vbb = sm + VP_OFF + buf * (64 * VROW) + 12 * (tq ^ (g & 3)) + 4 * wn;
#pragma unroll
    for (int dt = 0; dt < 8; ++dt) {
      uint4 vv = *reinterpret_cast<const uint4*>(vbb + VROW * (8 * dt + g));
      mma_f16(O[dt][0], O[dt][1], O[dt][2], O[dt][3],
              h2lo[0], h2hi[0], h2lo[1], h2hi[1], vv.x, vv.y);
      mma_f16(O[dt][0], O[dt][1], O[dt][2], O[dt][3],
              h2lo[2], h2hi[2], h2lo[3], h2hi[3], vv.z, vv.w);
    }
  }

  // ---- epilogue: sum the two n-half partial O's, normalize, store ----
  __syncthreads();
  float* ox = (float*)(sm + QP_OFF);  // reuse Q space (32 KB needed)
  if (wn == 1) {
    float* dst = ox + (wm * 32 + lane) * 32;
#pragma unroll
    for (int dt = 0; dt < 8; ++dt) {
#pragma unroll
      for (int c = 0; c < 4; ++c) dst[dt * 4 + c] = O[dt][c];
    }
  }
  __syncthreads();
  if (wn == 0) {
    const float* src = ox + (wm * 32 + lane) * 32;
    const float inv0 = 1.f / l0, inv1 = 1.f / l1;
    float* Ow = Og + (bh * Sc + q0 + 16 * wm) * (size_t)Dc;
#pragma unroll
    for (int dt = 0; dt < 8; ++dt) {
      float o0 = (O[dt][0] + src[dt * 4 + 0]) * inv0;
      float o1 = (O[dt][1] + src[dt * 4 + 1]) * inv0;
      float o2 = (O[dt][2] + src[dt * 4 + 2]) * inv1;
      float o3 = (O[dt][3] + src[dt * 4 + 3]) * inv1;
      int c = 8 * dt + 2 * tq;
      *reinterpret_cast<float2*>(Ow + (size_t)g * Dc + c) = make_float2(o0, o1);
      *reinterpret_cast<float2*>(Ow + (size_t)(g + 8) * Dc + c) = make_float2(o2, o3);
    }
  }
}

}  // namespace

extern "C" void kernel_launch(void* const* d_in, const int* in_sizes, int n_in,
                              void* d_out, int out_size) {
  const float* Q = (const float*)d_in[0];
  const float* K = (const float*)d_in[1];
  const float* V = (const float*)d_in[2];
  float* O = (float*)d_out;
  (void)in_sizes; (void)n_in; (void)out_size;

  constexpr int B = 4, H = 16;
  constexpr int smem_bytes = SMEM_WORDS * 4;  // 108544
  cudaFuncSetAttribute(fa_fwd, cudaFuncAttributeMaxDynamicSharedMemorySize, smem_bytes);

  dim3 grid(Sc / BM, B * H);
  fa_fwd<<<grid, NT, smem_bytes>>>(Q, K, V, O);
}

// round 17
// speedup vs baseline: 1.1431x; 1.1431x over previous
#include <cuda_runtime.h>
#include <cuda_fp16.h>

// Causal SDPA, B=4 H=16 S=2048 D=64, fp32.
// R13 (re-bench; prior submissions hit GPU-broker timeouts) = R9 (best
// measured: 311us) + double-buffered K/V smem and ONE barrier per tile
// instead of two (staging stores overlap softmax/PV). R11's 16-warp n-split
// regressed (381us): occupancy bought with cross-warp sync+instr overhead is
// a net loss. 8 warps, warp-local softmax, permuted smem layouts (LDS.128
// b-frags), tf32 QK + fp16 PV mma.sync, log2 softmax, poly exp2.

namespace {

constexpr int Sc = 2048;
constexpr int Dc = 64;
constexpr int BM = 128;  // Q rows per CTA (8 warps x 16 rows)
constexpr int BN = 64;   // KV rows per tile
constexpr int NT = 256;
constexpr int KROW = 80; // permuted K row stride (u32)
constexpr int VROW = 48; // permuted V^T row stride (u32)

// dynamic smem (u32 words): two K buffers then two V buffers
constexpr int KBUF = 64 * KROW;            // 5120 words
constexpr int VBUF = 64 * VROW;            // 3072 words
constexpr int SMEM_WORDS = 2 * KBUF + 2 * VBUF;  // 16384 words = 65536 B

#define QSCALE 0.180336880111120430f  // (1/sqrt(64)) * log2(e)
#define MAGICF 12582912.0f            // 1.5 * 2^23
#define EC1 0.6931471805599453f
#define EC2 0.2402265069591007f
#define EC3 0.0555041086648216f
#define EC4 0.0096181291076285f

typedef unsigned long long u64;
typedef unsigned int u32;

__device__ __forceinline__ u64 pack2(float lo, float hi) {
  u64 r;
  asm("mov.b64 %0, {%1, %2};" : "=l"(r) : "f"(lo), "f"(hi));
  return r;
}
__device__ __forceinline__ void unpack2(u64 v, float& lo, float& hi) {
  asm("mov.b64 {%0, %1}, %2;" : "=f"(lo), "=f"(hi) : "l"(v));
}
__device__ __forceinline__ u64 fma2o(u64 a, u64 b, u64 c) {
  u64 d;
  asm("fma.rn.f32x2 %0, %1, %2, %3;" : "=l"(d) : "l"(a), "l"(b), "l"(c));
  return d;
}
__device__ __forceinline__ u64 add2(u64 a, u64 b) {
  u64 d;
  asm("add.rn.f32x2 %0, %1, %2;" : "=l"(d) : "l"(a), "l"(b));
  return d;
}

__device__ __forceinline__ float exp2s(float d) {
  d = fmaxf(d, -80.0f);
  float t = d + MAGICF;
  float nf = t - MAGICF;
  float f = d - nf;
  float p = EC3 + f * EC4;
  p = EC2 + f * p;
  p = EC1 + f * p;
  p = 1.0f + f * p;
  return __int_as_float(__float_as_int(p) + (__float_as_int(t) << 23));
}

__device__ __forceinline__ void exp2p2(float d0, float d1, float& e0, float& e1) {
  u64 d2 = pack2(d0, d1);
  u64 t2 = add2(d2, pack2(MAGICF, MAGICF));
  u64 n2 = add2(t2, pack2(-MAGICF, -MAGICF));
  u64 f2 = fma2o(n2, pack2(-1.0f, -1.0f), d2);
  u64 p2 = fma2o(f2, pack2(EC4, EC4), pack2(EC3, EC3));
  p2 = fma2o(f2, p2, pack2(EC2, EC2));
  p2 = fma2o(f2, p2, pack2(EC1, EC1));
  p2 = fma2o(f2, p2, pack2(1.0f, 1.0f));
  float tf0, tf1, pf0, pf1;
  unpack2(t2, tf0, tf1);
  unpack2(p2, pf0, pf1);
  e0 = __int_as_float(__float_as_int(pf0) + (__float_as_int(tf0) << 23));
  e1 = __int_as_float(__float_as_int(pf1) + (__float_as_int(tf1) << 23));
}

__device__ __forceinline__ u32 cvt_tf32(float x) {
  u32 r;
  asm("cvt.rna.tf32.f32 %0, %1;" : "=r"(r) : "f"(x));
  return r;
}
__device__ __forceinline__ u32 h2pack(float lo, float hi) {
  __half2 h = __floats2half2_rn(lo, hi);
  return *reinterpret_cast<u32*>(&h);
}

__device__ __forceinline__ void mma_tf32(float& c0, float& c1, float& c2, float& c3,
                                         u32 a0, u32 a1, u32 a2, u32 a3,
                                         u32 b0, u32 b1) {
  asm("mma.sync.aligned.m16n8k8.row.col.f32.tf32.tf32.f32 "
      "{%0,%1,%2,%3}, {%4,%5,%6,%7}, {%8,%9}, {%0,%1,%2,%3};"
      : "+f"(c0), "+f"(c1), "+f"(c2), "+f"(c3)
      : "r"(a0), "r"(a1), "r"(a2), "r"(a3), "r"(b0), "r"(b1));
}
__device__ __forceinline__ void mma_f16(float& c0, float& c1, float& c2, float& c3,
                                        u32 a0, u32 a1, u32 a2, u32 a3,
                                        u32 b0, u32 b1) {
  asm("mma.sync.aligned.m16n8k16.row.col.f32.f16.f16.f32 "
      "{%0,%1,%2,%3}, {%4,%5,%6,%7}, {%8,%9}, {%0,%1,%2,%3};"
      : "+f"(c0), "+f"(c1), "+f"(c2), "+f"(c3)
      : "r"(a0), "r"(a1), "r"(a2), "r"(a3), "r"(b0), "r"(b1));
}

__global__ __launch_bounds__(NT, 1) void fa_fwd(
    const float* __restrict__ Qg, const float* __restrict__ Kg,
    const float* __restrict__ Vg, float* __restrict__ Og) {
  extern __shared__ __align__(16) u32 sm[];
  // sm[0 .. 2*KBUF)        : K buffers
  // sm[2*KBUF .. +2*VBUF)  : V buffers

  const int tid = threadIdx.x;
  const int w = tid >> 5;       // warp 0..7, rows 16w..16w+15
  const int lane = tid & 31;
  const int g = lane >> 2;      // 0..7
  const int tq = lane & 3;      // 0..3
  const int qt = (int)(gridDim.x - 1) - (int)blockIdx.x;  // long CTAs first
  const int q0 = qt * BM;
  const size_t bh = blockIdx.y;
  const float* Kb = Kg + bh * (size_t)(Sc * Dc);
  const float* Vb = Vg + bh * (size_t)(Sc * Dc);

  // staging maps
  const int kr = tid >> 4;            // K: row (+16*ii), cols kc4..kc4+3
  const int kc4 = (tid & 15) << 2;
  const int vnb = (tid & 15) << 2;    // V: rows vnb..+3, cols vdb..+3
  const int vdb = (tid >> 4) << 2;

  // mainloop smem bases (per thread)
  const int kbase0 = KROW * g + 20 * tq;       // + 640*j per column tile
  const int vxor = 12 * (tq ^ (g & 3));        // V block offset

  const int ntiles = 2 * qt + 2;

  // ---- prefetch tile 0 into registers ----
  float4 kp[4], vp[4];
#pragma unroll
  for (int ii = 0; ii < 4; ++ii)
    kp[ii] = *(const float4*)(Kb + (size_t)(kr + 16 * ii) * Dc + kc4);
#pragma unroll
  for (int i = 0; i < 4; ++i)
    vp[i] = *(const float4*)(Vb + (size_t)(vnb + i) * Dc + vdb);

  // ---- Q fragments (tf32, prescaled into log2 domain), registers only ----
  u32 qf[8][4];
  {
    const float* Qw = Qg + (bh * Sc + q0 + 16 * w) * (size_t)Dc;
#pragma unroll
    for (int s = 0; s < 8; ++s) {
      int c = 8 * s + tq;
      qf[s][0] = cvt_tf32(Qw[(size_t)g * Dc + c] * QSCALE);
      qf[s][1] = cvt_tf32(Qw[(size_t)(g + 8) * Dc + c] * QSCALE);
      qf[s][2] = cvt_tf32(Qw[(size_t)g * Dc + c + 4] * QSCALE);
      qf[s][3] = cvt_tf32(Qw[(size_t)(g + 8) * Dc + c + 4] * QSCALE);
    }
  }
  const int r0 = q0 + 16 * w + g;  // this thread's two rows: r0, r0+8

  // ---- store tile 0 into buffer 0, one barrier ----
  {
    u32* Kd = sm;
    u32* Vd = sm + 2 * KBUF;
#pragma unroll
    for (int ii = 0; ii < 4; ++ii) {
      int row = kr + 16 * ii;
      int base = KROW * row + (kc4 >> 2);
      Kd[base + 0]  = cvt_tf32(kp[ii].x);
      Kd[base + 20] = cvt_tf32(kp[ii].y);
      Kd[base + 40] = cvt_tf32(kp[ii].z);
      Kd[base + 60] = cvt_tf32(kp[ii].w);
    }
#pragma unroll
    for (int j = 0; j < 4; ++j) {
      int r = vdb + j;
      int x = r & 3;
      int i0 = vnb >> 1;
      Vd[VROW * r + 12 * ((i0 & 3) ^ x) + (i0 >> 2)] =
          h2pack((&vp[0].x)[j], (&vp[1].x)[j]);
      Vd[VROW * r + 12 * (((i0 + 1) & 3) ^ x) + ((i0 + 1) >> 2)] =
          h2pack((&vp[2].x)[j], (&vp[3].x)[j]);
    }
  }
  __syncthreads();

  float O[8][4];
#pragma unroll
  for (int dt = 0; dt < 8; ++dt)
#pragma unroll
    for (int c = 0; c < 4; ++c) O[dt][c] = 0.f;
  float m0 = -1e30f, m1 = -1e30f, l0 = 0.f, l1 = 0.f;

  for (int t = 0; t < ntiles; ++t) {
    const int buf = t & 1;
    const int n0 = t * BN;
    const u32* Kcur = sm + buf * KBUF;
    const u32* Vcur = sm + 2 * KBUF + buf * VBUF;
    const bool havenext = (t + 1 < ntiles);

    // ---- prefetch tile t+1 from gmem into registers ----
    if (havenext) {
      const int nn = (t + 1) * BN;
#pragma unroll
      for (int ii = 0; ii < 4; ++ii)
        kp[ii] = *(const float4*)(Kb + (size_t)(nn + kr + 16 * ii) * Dc + kc4);
#pragma unroll
      for (int i = 0; i < 4; ++i)
        vp[i] = *(const float4*)(Vb + (size_t)(nn + vnb + i) * Dc + vdb);
    }

    // ---- S = Q @ K^T (tf32 tensor MMAs; block-loaded b-frags) ----
    float acc[8][4];
#pragma unroll
    for (int j = 0; j < 8; ++j)
#pragma unroll
      for (int c = 0; c < 4; ++c) acc[j][c] = 0.f;

#pragma unroll
    for (int j = 0; j < 8; ++j) {
      const u32* kb_ = Kcur + kbase0 + 640 * j;  // 640 = 8*KROW
      uint4 w0 = *reinterpret_cast<const uint4*>(kb_ + 0);
      uint4 w1 = *reinterpret_cast<const uint4*>(kb_ + 4);
      uint4 w2 = *reinterpret_cast<const uint4*>(kb_ + 8);
      uint4 w3 = *reinterpret_cast<const uint4*>(kb_ + 12);
      u32 kw[16] = {w0.x, w0.y, w0.z, w0.w, w1.x, w1.y, w1.z, w1.w,
                    w2.x, w2.y, w2.z, w2.w, w3.x, w3.y, w3.z, w3.w};
#pragma unroll
      for (int s = 0; s < 8; ++s)
        mma_tf32(acc[j][0], acc[j][1], acc[j][2], acc[j][3],
                 qf[s][0], qf[s][1], qf[s][2], qf[s][3], kw[2 * s], kw[2 * s + 1]);
    }

    // ---- online softmax on fragments (log2 domain) ----
    if (n0 + BN - 1 > q0) {  // tile touches the diagonal
#pragma unroll
      for (int j = 0; j < 8; ++j) {
        int col = n0 + 8 * j + 2 * tq;
        if (col > r0) acc[j][0] = -1e30f;
        if (col + 1 > r0) acc[j][1] = -1e30f;
        if (col > r0 + 8) acc[j][2] = -1e30f;
        if (col + 1 > r0 + 8) acc[j][3] = -1e30f;
      }
    }
    float mt0 = acc[0][0], mt1 = acc[0][2];
#pragma unroll
    for (int j = 0; j < 8; ++j) {
      mt0 = fmaxf(mt0, fmaxf(acc[j][0], acc[j][1]));
      mt1 = fmaxf(mt1, fmaxf(acc[j][2], acc[j][3]));
    }
    mt0 = fmaxf(mt0, __shfl_xor_sync(0xffffffffu, mt0, 1));
    mt0 = fmaxf(mt0, __shfl_xor_sync(0xffffffffu, mt0, 2));
    mt1 = fmaxf(mt1, __shfl_xor_sync(0xffffffffu, mt1, 1));
    mt1 = fmaxf(mt1, __shfl_xor_sync(0xffffffffu, mt1, 2));
    const float mn0 = fmaxf(m0, mt0), mn1 = fmaxf(m1, mt1);
    const float al0 = exp2s(m0 - mn0), al1 = exp2s(m1 - mn1);
    m0 = mn0;
    m1 = mn1;

    float rs0 = 0.f, rs1 = 0.f;
    u32 h2lo[8], h2hi[8];  // fp16 P fragments
#pragma unroll
    for (int j = 0; j < 8; ++j) {
      float e0, e1, e2, e3;
      exp2p2(fmaxf(acc[j][0] - mn0, -80.f), fmaxf(acc[j][1] - mn0, -80.f), e0, e1);
      exp2p2(fmaxf(acc[j][2] - mn1, -80.f), fmaxf(acc[j][3] - mn1, -80.f), e2, e3);
      rs0 += e0 + e1;
      rs1 += e2 + e3;
      h2lo[j] = h2pack(e0, e1);
      h2hi[j] = h2pack(e2, e3);
    }
    rs0 += __shfl_xor_sync(0xffffffffu, rs0, 1);
    rs0 += __shfl_xor_sync(0xffffffffu, rs0, 2);
    rs1 += __shfl_xor_sync(0xffffffffu, rs1, 1);
    rs1 += __shfl_xor_sync(0xffffffffu, rs1, 2);
    l0 = l0 * al0 + rs0;
    l1 = l1 * al1 + rs1;
#pragma unroll
    for (int dt = 0; dt < 8; ++dt) {
      O[dt][0] *= al0;
      O[dt][1] *= al0;
      O[dt][2] *= al1;
      O[dt][3] *= al1;
    }

    // ---- store prefetched tile t+1 into the ALTERNATE buffers ----
    // (overlaps with PV below; visibility guaranteed by the tail barrier)
    if (havenext) {
      u32* Kd = sm + (buf ^ 1) * KBUF;
      u32* Vd = sm + 2 * KBUF + (buf ^ 1) * VBUF;
#pragma unroll
      for (int ii = 0; ii < 4; ++ii) {
        int row = kr + 16 * ii;
        int base = KROW * row + (kc4 >> 2);
        Kd[base + 0]  = cvt_tf32(kp[ii].x);
        Kd[base + 20] = cvt_tf32(kp[ii].y);
        Kd[base + 40] = cvt_tf32(kp[ii].z);
        Kd[base + 60] = cvt_tf32(kp[ii].w);
      }
#pragma unroll
      for (int j = 0; j < 4; ++j) {
        int r = vdb + j;
        int x = r & 3;
        int i0 = vnb >> 1;
        Vd[VROW * r + 12 * ((i0 & 3) ^ x) + (i0 >> 2)] =
            h2pack((&vp[0].x)[j], (&vp[1].x)[j]);
        Vd[VROW * r + 12 * (((i0 + 1) & 3) ^ x) + ((i0 + 1) >> 2)] =
            h2pack((&vp[2].x)[j], (&vp[3].x)[j]);
      }
    }

    // ---- O += P @ V (fp16 tensor MMAs; block-loaded b-frags) ----
#pragma unroll
    for (int dt = 0; dt < 8; ++dt) {
      const u32* vb_ = Vcur + VROW * (8 * dt + g) + vxor;
      uint4 a4 = *reinterpret_cast<const uint4*>(vb_ + 0);
      uint4 b4 = *reinterpret_cast<const uint4*>(vb_ + 4);
      u32 vw[8] = {a4.x, a4.y, a4.z, a4.w, b4.x, b4.y, b4.z, b4.w};
#pragma unroll
      for (int u = 0; u < 4; ++u)
        mma_f16(O[dt][0], O[dt][1], O[dt][2], O[dt][3],
                h2lo[2 * u], h2hi[2 * u], h2lo[2 * u + 1], h2hi[2 * u + 1],
                vw[2 * u], vw[2 * u + 1]);
    }
    __syncthreads();  // single barrier: t+1 stores visible, buf reuse safe
  }

  // ---- epilogue: normalize and store ----
  const float inv0 = 1.f / l0, inv1 = 1.f / l1;
  float* Ow = Og + (bh * Sc + q0 + 16 * w) * (size_t)Dc;
#pragma unroll
  for (int dt = 0; dt < 8; ++dt) {
    int c = 8 * dt + 2 * tq;
    *reinterpret_cast<float2*>(Ow + (size_t)g * Dc + c) =
        make_float2(O[dt][0] * inv0, O[dt][1] * inv0);
    *reinterpret_cast<float2*>(Ow + (size_t)(g + 8) * Dc + c) =
        make_float2(O[dt][2] * inv1, O[dt][3] * inv1);
  }
}

}  // namespace

extern "C" void kernel_launch(void* const* d_in, const int* in_sizes, int n_in,
                              void* d_out, int out_size) {
  const float* Q = (const float*)d_in[0];
  const float* K = (const float*)d_in[1];
  const float* V = (const float*)d_in[2];
  float* O = (float*)d_out;
  (void)in_sizes; (void)n_in; (void)out_size;

  constexpr int B = 4, H = 16;
  constexpr int smem_bytes = SMEM_WORDS * 4;  // 65536
  cudaFuncSetAttribute(fa_fwd, cudaFuncAttributeMaxDynamicSharedMemorySize, smem_bytes);

  dim3 grid(Sc / BM, B * H);
  fa_fwd<<<grid, NT, smem_bytes>>>(Q, K, V, O);
}